// round 4
// baseline (speedup 1.0000x reference)
#include <cuda_runtime.h>
#include <cuda_bf16.h>
#include <math.h>
#include <stdint.h>

#define SSP 16129   // 127*127
#define HW  127
#define BB  4
#define CC  256
#define IMG 256
#define IMGSZ 65536

// ---------------- scratch (device globals; no allocation) ----------------
__device__ float g_xd[BB*CC*SSP];                               // downsampled x  [b][c][s]  fp32
__device__ __align__(16) __nv_bfloat16 g_xdb[(size_t)BB*SSP*CC];// xd transposed  [b][s][c]  bf16
__device__ float g_qk[BB*SSP*64];                               // q(0..31)|k(32..63) [b][s][64]
__device__ float g_a [BB*SSP*64];                               // resized attn  [b][s][64]
__device__ float g_E [(size_t)BB*SSP*256];                      // energies (padded rows of 256)
__device__ float g_A [(size_t)BB*SSP*256];                      // a-energies
__device__ __align__(16) __nv_bfloat16 g_S [(size_t)BB*SSP*256];     // softmax result bf16
__device__ __align__(16) __nv_bfloat16 g_vW[(size_t)BB*HW*CC*128];   // v as [b][i][c][j(pad128)]
__device__ __align__(16) __nv_bfloat16 g_vH[(size_t)BB*HW*CC*128];   // v as [b][j][c][i(pad128)]
__device__ __align__(16) __nv_bfloat16 g_oH[(size_t)BB*CC*HW*128];   // outH [b][c][j][i(pad128)]
__device__ __align__(16) __nv_bfloat16 g_oW[(size_t)BB*CC*HW*128];   // outW [b][c][i][j(pad128)]

// ---------------- mma.sync helper (bf16 HMMA, compute_103-legal) ----------------
__device__ __forceinline__ void mma16816(float c[4],
                                         uint32_t a0, uint32_t a1, uint32_t a2, uint32_t a3,
                                         uint32_t b0, uint32_t b1) {
    asm volatile(
        "mma.sync.aligned.m16n8k16.row.col.f32.bf16.bf16.f32 "
        "{%0,%1,%2,%3}, {%4,%5,%6,%7}, {%8,%9}, {%0,%1,%2,%3};"
        : "+f"(c[0]), "+f"(c[1]), "+f"(c[2]), "+f"(c[3])
        : "r"(a0), "r"(a1), "r"(a2), "r"(a3), "r"(b0), "r"(b1));
}

// warp computes 32x64 of the 128x128 CTA tile over a 64-deep k-chunk.
// As: [128][72] bf16 (m rows, k contiguous). Bs: [128][72] bf16 (n rows, k contiguous).
__device__ __forceinline__ void warp_mma_chunk(const __nv_bfloat16* As, const __nv_bfloat16* Bs,
                                               float acc[2][8][4], int M0, int N0, int g, int t) {
    #pragma unroll
    for (int k16 = 0; k16 < 4; k16++) {
        int kb = k16*16;
        uint32_t a[2][4];
        #pragma unroll
        for (int f = 0; f < 2; f++) {
            int r = M0 + f*16 + g;
            a[f][0] = *(const uint32_t*)&As[r*72 + kb + t*2];
            a[f][1] = *(const uint32_t*)&As[(r+8)*72 + kb + t*2];
            a[f][2] = *(const uint32_t*)&As[r*72 + kb + t*2 + 8];
            a[f][3] = *(const uint32_t*)&As[(r+8)*72 + kb + t*2 + 8];
        }
        #pragma unroll
        for (int j = 0; j < 8; j++) {
            int rb = N0 + j*8 + g;
            uint32_t b0 = *(const uint32_t*)&Bs[rb*72 + kb + t*2];
            uint32_t b1 = *(const uint32_t*)&Bs[rb*72 + kb + t*2 + 8];
            #pragma unroll
            for (int f = 0; f < 2; f++)
                mma16816(acc[f][j], a[f][0], a[f][1], a[f][2], a[f][3], b0, b1);
        }
    }
}

// ---------------- f32x2 helpers (fp32 path) ----------------
__device__ __forceinline__ unsigned long long dup2(float x) {
    unsigned long long r;
    asm("mov.b64 %0, {%1, %1};" : "=l"(r) : "f"(x));
    return r;
}
__device__ __forceinline__ void fma2(unsigned long long& d, unsigned long long a, unsigned long long b) {
    asm("fma.rn.f32x2 %0, %1, %2, %0;" : "+l"(d) : "l"(a), "l"(b));
}
__device__ __forceinline__ float2 unpack2(unsigned long long v) {
    float2 r;
    asm("mov.b64 {%0, %1}, %2;" : "=f"(r.x), "=f"(r.y) : "l"(v));
    return r;
}

__device__ __forceinline__ void micro128(const float* As, const float* Bs,
                                         unsigned long long acc[8][4], int tx, int ty) {
    #pragma unroll
    for (int kk = 0; kk < 16; kk++) {
        float4 x0 = *(const float4*)&As[kk*132 + tx*4];
        float4 x1 = *(const float4*)&As[kk*132 + 64 + tx*4];
        ulonglong2 w0 = *(const ulonglong2*)&Bs[kk*132 + ty*8];
        ulonglong2 w1 = *(const ulonglong2*)&Bs[kk*132 + ty*8 + 4];
        unsigned long long xs[8];
        xs[0]=dup2(x0.x); xs[1]=dup2(x0.y); xs[2]=dup2(x0.z); xs[3]=dup2(x0.w);
        xs[4]=dup2(x1.x); xs[5]=dup2(x1.y); xs[6]=dup2(x1.z); xs[7]=dup2(x1.w);
        #pragma unroll
        for (int m = 0; m < 8; m++) {
            fma2(acc[m][0], xs[m], w0.x);
            fma2(acc[m][1], xs[m], w0.y);
            fma2(acc[m][2], xs[m], w1.x);
            fma2(acc[m][3], xs[m], w1.y);
        }
    }
}
__device__ __forceinline__ void micro64(const float* As, const float* Bs,
                                        unsigned long long acc[8][2], int tx, int ty) {
    #pragma unroll
    for (int kk = 0; kk < 16; kk++) {
        float4 x0 = *(const float4*)&As[kk*132 + tx*4];
        float4 x1 = *(const float4*)&As[kk*132 + 64 + tx*4];
        ulonglong2 w0 = *(const ulonglong2*)&Bs[kk*68 + ty*4];
        unsigned long long xs[8];
        xs[0]=dup2(x0.x); xs[1]=dup2(x0.y); xs[2]=dup2(x0.z); xs[3]=dup2(x0.w);
        xs[4]=dup2(x1.x); xs[5]=dup2(x1.y); xs[6]=dup2(x1.z); xs[7]=dup2(x1.w);
        #pragma unroll
        for (int m = 0; m < 8; m++) {
            fma2(acc[m][0], xs[m], w0.x);
            fma2(acc[m][1], xs[m], w0.y);
        }
    }
}

// ---------------- 1) depthwise 4x4 stride-2 conv ----------------
__global__ void conv_down_kernel(const float* __restrict__ x, const float* __restrict__ wd) {
    int idx = blockIdx.x * blockDim.x + threadIdx.x;
    if (idx >= BB*CC*SSP) return;
    int j  = idx % HW;
    int i  = (idx / HW) % HW;
    int bc = idx / SSP;
    int c  = bc % CC;
    const float* px = x + (size_t)bc * IMGSZ + (2*i) * IMG + 2*j;
    const float* w  = wd + c * 16;
    float s = 0.f;
    #pragma unroll
    for (int dy = 0; dy < 4; dy++)
        #pragma unroll
        for (int dx = 0; dx < 4; dx++)
            s += px[dy*IMG + dx] * w[dy*4 + dx];
    g_xd[idx] = s;
}

// ---------------- 2) xd [c][s] fp32 -> xdb [s][c] bf16 ----------------
__global__ __launch_bounds__(256) void xd_to_bf16_kernel() {
    __shared__ float t[32][129];
    int s0 = blockIdx.x * 128, b = blockIdx.y;
    int tid = threadIdx.x;
    for (int c0 = 0; c0 < 256; c0 += 32) {
        #pragma unroll
        for (int p = 0; p < 16; p++) {
            int e = tid + p*256;
            int cc = e >> 7, ss = e & 127;
            int s = s0 + ss;
            t[cc][ss] = (s < SSP) ? g_xd[((size_t)(b*256) + c0 + cc)*SSP + s] : 0.f;
        }
        __syncthreads();
        #pragma unroll
        for (int p = 0; p < 16; p++) {
            int e = tid + p*256;
            int ss = e >> 5, cc = e & 31;
            int s = s0 + ss;
            if (s < SSP)
                g_xdb[((size_t)b*SSP + s)*256 + c0 + cc] = __float2bfloat16(t[cc][ss]);
        }
        __syncthreads();
    }
}

// ---------------- 3) bilinear downsample of attention_map -> g_a [b][s][64] ----------------
__global__ __launch_bounds__(256) void resize_a_kernel(const float* __restrict__ am) {
    __shared__ float t[32][65];
    int b = blockIdx.z, i = blockIdx.y, j0 = blockIdx.x * 32;
    const float sc = 255.f / 126.f;
    float yf = i * sc; int y0 = (int)yf; float wy = yf - y0; int y1 = min(y0+1, IMG-1);
    #pragma unroll
    for (int it = 0; it < 8; it++) {
        int e = threadIdx.x + it*256;
        int ca = e >> 5, jj = e & 31;
        int j = j0 + jj;
        if (j < HW) {
            float xf = j * sc; int x0 = (int)xf; float wx = xf - x0; int x1 = min(x0+1, IMG-1);
            const float* P = am + ((size_t)(b*64 + ca)) * IMGSZ;
            float v = (P[y0*IMG+x0]*(1.f-wx) + P[y0*IMG+x1]*wx) * (1.f-wy)
                    + (P[y1*IMG+x0]*(1.f-wx) + P[y1*IMG+x1]*wx) * wy;
            t[jj][ca] = v;
        }
    }
    __syncthreads();
    #pragma unroll
    for (int it = 0; it < 8; it++) {
        int e = threadIdx.x + it*256;
        int jj = e >> 6, ca = e & 63;
        int j = j0 + jj;
        if (j < HW)
            g_a[((size_t)b*SSP + i*HW + j)*64 + ca] = t[jj][ca];
    }
}

// ---------------- 4) fused Q|K projection (f32x2) ----------------
__global__ __launch_bounds__(256) void proj_qk_kernel(const float* __restrict__ wq, const float* __restrict__ bq,
                                                      const float* __restrict__ wk, const float* __restrict__ bk) {
    __shared__ __align__(16) float As[16*132];
    __shared__ __align__(16) float Bs[16*68];
    int s0 = blockIdx.x * 128, b = blockIdx.y;
    int tid = threadIdx.x, tx = tid & 15, ty = tid >> 4;
    unsigned long long acc[8][2] = {};
    const float* Xb = g_xd + (size_t)b * CC * SSP;
    for (int k0 = 0; k0 < 256; k0 += 16) {
        #pragma unroll
        for (int i = 0; i < 8; i++) {
            int e = tid + i*256;
            int kk = e >> 7, mm = e & 127;
            int s = s0 + mm;
            As[kk*132 + mm] = (s < SSP) ? Xb[(size_t)(k0+kk)*SSP + s] : 0.f;
        }
        #pragma unroll
        for (int i = 0; i < 4; i++) {
            int e = tid + i*256;
            int nn = e >> 4, kk = e & 15;
            Bs[kk*68 + nn] = (nn < 32) ? wq[nn*256 + k0 + kk] : wk[(nn-32)*256 + k0 + kk];
        }
        __syncthreads();
        micro64(As, Bs, acc, tx, ty);
        __syncthreads();
    }
    int nb = ty*4;
    float bv[4];
    #pragma unroll
    for (int ni = 0; ni < 4; ni++) {
        int n = nb + ni;
        bv[ni] = (n < 32) ? bq[n] : bk[n-32];
    }
    #pragma unroll
    for (int mi = 0; mi < 8; mi++) {
        int s = s0 + ((mi < 4) ? tx*4 + mi : 64 + tx*4 + mi - 4);
        if (s >= SSP) continue;
        float2 p0 = unpack2(acc[mi][0]), p1 = unpack2(acc[mi][1]);
        float* o = g_qk + ((size_t)b*SSP + s)*64 + nb;
        *(float4*)o = make_float4(p0.x+bv[0], p0.y+bv[1], p1.x+bv[2], p1.y+bv[3]);
    }
}

// ---------------- 5) V projection on HMMA tensor cores -> g_vW ----------------
// CTA: M=128 spatial rows, N=128 channels (grid.y half), K=256.
__global__ __launch_bounds__(256) void proj_v_mma_kernel(const float* __restrict__ W,
                                                         const float* __restrict__ bias) {
    __shared__ __align__(16) char smbuf[36864];
    __shared__ float biass[128];
    __nv_bfloat16* As = (__nv_bfloat16*)smbuf;              // [128][72]
    __nv_bfloat16* Bs = (__nv_bfloat16*)(smbuf + 18432);    // [128][72]
    int tid = threadIdx.x, wid = tid >> 5, lane = tid & 31;
    int g = lane >> 2, t = lane & 3;
    int s0 = blockIdx.x * 128, n0 = blockIdx.y * 128, b = blockIdx.z;
    if (tid < 128) biass[tid] = bias[n0 + tid];
    float acc[2][8][4] = {};
    int M0 = (wid >> 1) * 32, N0 = (wid & 1) * 64;

    for (int kc = 0; kc < 4; kc++) {
        #pragma unroll
        for (int it = 0; it < 4; it++) {
            int u = tid + it*256;
            int m = u >> 3, seg = u & 7;
            int s = s0 + m;
            uint4 val = make_uint4(0,0,0,0);
            if (s < SSP) val = *(const uint4*)&g_xdb[((size_t)b*SSP + s)*256 + kc*64 + seg*8];
            *(uint4*)&As[m*72 + seg*8] = val;
        }
        #pragma unroll
        for (int it = 0; it < 4; it++) {
            int u = tid + it*256;
            int n = u >> 3, seg = u & 7;
            const float* src = &W[(size_t)(n0+n)*256 + kc*64 + seg*8];
            float4 f0 = *(const float4*)src, f1 = *(const float4*)(src+4);
            __nv_bfloat162 p0 = __float22bfloat162_rn(make_float2(f0.x, f0.y));
            __nv_bfloat162 p1 = __float22bfloat162_rn(make_float2(f0.z, f0.w));
            __nv_bfloat162 p2 = __float22bfloat162_rn(make_float2(f1.x, f1.y));
            __nv_bfloat162 p3 = __float22bfloat162_rn(make_float2(f1.z, f1.w));
            uint4 val;
            val.x = *(uint32_t*)&p0; val.y = *(uint32_t*)&p1;
            val.z = *(uint32_t*)&p2; val.w = *(uint32_t*)&p3;
            *(uint4*)&Bs[n*72 + seg*8] = val;
        }
        __syncthreads();
        warp_mma_chunk(As, Bs, acc, M0, N0, g, t);
        __syncthreads();
    }

    // stage D as [n][m] bf16 (with bias), then coalesced scatter to vW
    __nv_bfloat16* stage = (__nv_bfloat16*)smbuf;           // [128][136]
    #pragma unroll
    for (int f = 0; f < 2; f++)
        #pragma unroll
        for (int j = 0; j < 8; j++) {
            int m = M0 + f*16 + g, n = N0 + j*8 + t*2;
            stage[n*136 + m]         = __float2bfloat16(acc[f][j][0] + biass[n]);
            stage[(n+1)*136 + m]     = __float2bfloat16(acc[f][j][1] + biass[n+1]);
            stage[n*136 + m + 8]     = __float2bfloat16(acc[f][j][2] + biass[n]);
            stage[(n+1)*136 + m + 8] = __float2bfloat16(acc[f][j][3] + biass[n+1]);
        }
    __syncthreads();
    #pragma unroll
    for (int it = 0; it < 64; it++) {
        int u = it*256 + tid;
        int c = u >> 7, m = u & 127;
        int s = s0 + m;
        if (s < SSP) {
            int i = s / HW, j = s - i*HW;
            g_vW[(((size_t)(b*HW + i))*256 + n0 + c)*128 + j] = stage[c*136 + m];
        }
    }
}

// ---------------- 6) vW -> vH transpose ([i][c][j] -> [j][c][i]) ----------------
__global__ __launch_bounds__(256) void vh_transpose_kernel() {
    __shared__ __nv_bfloat16 t[32][33];
    int tile = blockIdx.x;          // 0..15 : (it, jt)
    int it = tile >> 2, jt = tile & 3;
    int c0 = blockIdx.y * 32, b = blockIdx.z;
    int i0 = it*32, j0 = jt*32;
    int tid = threadIdx.x, lane = tid & 31, grp = tid >> 5;
    for (int cc = 0; cc < 32; cc++) {
        int c = c0 + cc;
        #pragma unroll
        for (int p = 0; p < 4; p++) {
            int ii = grp + p*8;
            int i = i0 + ii, j = j0 + lane;
            __nv_bfloat16 v = __float2bfloat16(0.f);
            if (i <= 126)
                v = g_vW[(((size_t)(b*HW + i)*256) + c)*128 + j];
            t[ii][lane] = v;
        }
        __syncthreads();
        #pragma unroll
        for (int p = 0; p < 4; p++) {
            int jj = grp + p*8;
            int j = j0 + jj, i = i0 + lane;
            if (j <= 126)
                g_vH[(((size_t)(b*HW + j)*256) + c)*128 + i] = t[lane][jj];
        }
        __syncthreads();
    }
}

// ---------------- 7) energy GEMMs (f32x2) ----------------
template<int KDIM, bool MODEW, bool MASK>
__global__ __launch_bounds__(256) void energy_kernel() {
    __shared__ __align__(16) float As[16*132];
    __shared__ __align__(16) float Bs[16*132];
    const float* SRC = (KDIM == 32) ? g_qk : g_a;
    float* OUT       = (KDIM == 32) ? g_E  : g_A;
    const int qoff = 0, koff = (KDIM == 32) ? 32 : 0;
    int fix = blockIdx.x, b = blockIdx.y;
    int tid = threadIdx.x, tx = tid & 15, ty = tid >> 4;
    unsigned long long acc[8][4] = {};
    const float* S = SRC + (size_t)b * SSP * 64;
    #pragma unroll
    for (int k0 = 0; k0 < KDIM; k0 += 16) {
        #pragma unroll
        for (int i = 0; i < 8; i++) {
            int e = tid + i*256;
            int mm = e >> 4, kk = e & 15;
            int sp = MODEW ? fix*HW + mm : mm*HW + fix;
            float qa = 0.f, kb = 0.f;
            if (mm < HW) {
                qa = S[(size_t)sp*64 + qoff + k0 + kk];
                kb = S[(size_t)sp*64 + koff + k0 + kk];
            }
            As[kk*132 + mm] = qa;
            Bs[kk*132 + mm] = kb;
        }
        __syncthreads();
        micro128(As, Bs, acc, tx, ty);
        __syncthreads();
    }
    const int noff = MODEW ? 128 : 0;
    #pragma unroll
    for (int mi = 0; mi < 8; mi++) {
        int m = (mi < 4) ? tx*4 + mi : 64 + tx*4 + mi - 4;
        if (m >= HW) continue;
        size_t row = MODEW ? ((size_t)(b*HW + fix)*HW + m) : ((size_t)(b*HW + m)*HW + fix);
        float v[8];
        #pragma unroll
        for (int np = 0; np < 4; np++) {
            float2 p = unpack2(acc[mi][np]);
            v[np*2] = p.x; v[np*2+1] = p.y;
        }
        #pragma unroll
        for (int ni = 0; ni < 8; ni++) {
            int n = ty*8 + ni;
            if (n == HW) v[ni] = -INFINITY;
            if (MASK && n == m) v[ni] = -INFINITY;
        }
        float* o = OUT + row*256 + noff + ty*8;
        *(float4*)o     = make_float4(v[0], v[1], v[2], v[3]);
        *(float4*)(o+4) = make_float4(v[4], v[5], v[6], v[7]);
    }
}

// ---------------- 8) fused triple softmax -> g_S (bf16) ----------------
__device__ __forceinline__ float wmax(float v) {
    #pragma unroll
    for (int o = 16; o; o >>= 1) v = fmaxf(v, __shfl_xor_sync(0xffffffffu, v, o));
    return v;
}
__device__ __forceinline__ float wsum(float v) {
    #pragma unroll
    for (int o = 16; o; o >>= 1) v += __shfl_xor_sync(0xffffffffu, v, o);
    return v;
}
__global__ __launch_bounds__(256) void softmax3_kernel() {
    int w = threadIdx.x >> 5, lane = threadIdx.x & 31;
    size_t row = (size_t)blockIdx.x * 8 + w;
    if (row >= (size_t)BB*SSP) return;
    const float* Er = g_E + row*256;
    const float* Ar = g_A + row*256;
    float4 e0 = ((const float4*)Er)[lane];
    float4 e1 = ((const float4*)Er)[32 + lane];
    float4 a0 = ((const float4*)Ar)[lane];
    float4 a1 = ((const float4*)Ar)[32 + lane];
    float ev[8] = {e0.x,e0.y,e0.z,e0.w,e1.x,e1.y,e1.z,e1.w};
    float av[8] = {a0.x,a0.y,a0.z,a0.w,a1.x,a1.y,a1.z,a1.w};

    float m1 = -INFINITY, m2 = -INFINITY;
    #pragma unroll
    for (int i = 0; i < 8; i++) { m1 = fmaxf(m1, ev[i]); m2 = fmaxf(m2, av[i]); }
    m1 = wmax(m1); m2 = wmax(m2);
    float ce[8], ca[8], s1 = 0.f, s2 = 0.f;
    #pragma unroll
    for (int i = 0; i < 8; i++) {
        ce[i] = __expf(ev[i] - m1); s1 += ce[i];
        ca[i] = __expf(av[i] - m2); s2 += ca[i];
    }
    s1 = wsum(s1); s2 = wsum(s2);
    float r12 = 1.f / (s1 * s2);

    float pv[8];
    #pragma unroll
    for (int i = 0; i < 8; i++) pv[i] = ce[i] * ca[i] * r12;
    if (lane == 31) { pv[3] = -INFINITY; pv[7] = -INFINITY; }   // pad slots 127, 255

    float m3 = -INFINITY;
    #pragma unroll
    for (int i = 0; i < 8; i++) m3 = fmaxf(m3, pv[i]);
    m3 = wmax(m3);
    float s3 = 0.f, ov[8];
    #pragma unroll
    for (int i = 0; i < 8; i++) { ov[i] = __expf(pv[i] - m3); s3 += ov[i]; }
    s3 = wsum(s3);
    float r3 = 1.f / s3;

    __nv_bfloat16* Sr = g_S + row*256;
    __nv_bfloat162 q0 = __float22bfloat162_rn(make_float2(ov[0]*r3, ov[1]*r3));
    __nv_bfloat162 q1 = __float22bfloat162_rn(make_float2(ov[2]*r3, ov[3]*r3));
    __nv_bfloat162 q2 = __float22bfloat162_rn(make_float2(ov[4]*r3, ov[5]*r3));
    __nv_bfloat162 q3 = __float22bfloat162_rn(make_float2(ov[6]*r3, ov[7]*r3));
    uint2 u0 = make_uint2(*(uint32_t*)&q0, *(uint32_t*)&q1);
    uint2 u1 = make_uint2(*(uint32_t*)&q2, *(uint32_t*)&q3);
    ((uint2*)Sr)[lane]      = u0;
    ((uint2*)Sr)[32 + lane] = u1;
}

// ---------------- 9) out GEMMs on HMMA tensor cores ----------------
// MODEW=false (H): per (b, j=fix): D[m=i][c] = sum_l S[b,i,fix][l] * vH[b,fix,c,l]   -> oH[b][c][fix][i]
// MODEW=true  (W): per (b, i=fix): D[m=j][c] = sum_u S[b,fix,j][128+u] * vW[b,fix,c,u] -> oW[b][c][fix][j]
template<bool MODEW>
__global__ __launch_bounds__(256) void outgemm_mma_kernel() {
    __shared__ __align__(16) char smbuf[36864];
    __nv_bfloat16* As = (__nv_bfloat16*)smbuf;              // [128][72] : S rows
    __nv_bfloat16* Bs = (__nv_bfloat16*)(smbuf + 18432);    // [128][72] : V rows
    int tid = threadIdx.x, wid = tid >> 5, lane = tid & 31;
    int g = lane >> 2, t = lane & 3;
    int fix = blockIdx.x, n0 = blockIdx.y * 128, b = blockIdx.z;
    const __nv_bfloat16* V = MODEW ? g_vW : g_vH;
    __nv_bfloat16* O = MODEW ? g_oW : g_oH;
    const int noff = MODEW ? 128 : 0;
    float acc[2][8][4] = {};
    int M0 = (wid >> 1) * 32, N0 = (wid & 1) * 64;

    for (int kc = 0; kc < 2; kc++) {
        #pragma unroll
        for (int it = 0; it < 4; it++) {
            int u = tid + it*256;
            int m = u >> 3, seg = u & 7;
            uint4 val = make_uint4(0,0,0,0);
            if (m < HW) {
                size_t row = MODEW ? ((size_t)(b*HW + fix)*HW + m) : ((size_t)(b*HW + m)*HW + fix);
                val = *(const uint4*)&g_S[row*256 + noff + kc*64 + seg*8];
            }
            *(uint4*)&As[m*72 + seg*8] = val;
        }
        #pragma unroll
        for (int it = 0; it < 4; it++) {
            int u = tid + it*256;
            int n = u >> 3, seg = u & 7;
            uint4 val = *(const uint4*)&V[((size_t)(b*HW + fix)*256 + n0 + n)*128 + kc*64 + seg*8];
            *(uint4*)&Bs[n*72 + seg*8] = val;
        }
        __syncthreads();
        warp_mma_chunk(As, Bs, acc, M0, N0, g, t);
        __syncthreads();
    }

    // stage [n][m] bf16, then fully-coalesced uint4 stores
    __nv_bfloat16* stage = (__nv_bfloat16*)smbuf;           // [128][136]
    #pragma unroll
    for (int f = 0; f < 2; f++)
        #pragma unroll
        for (int j = 0; j < 8; j++) {
            int m = M0 + f*16 + g, n = N0 + j*8 + t*2;
            stage[n*136 + m]         = __float2bfloat16(acc[f][j][0]);
            stage[(n+1)*136 + m]     = __float2bfloat16(acc[f][j][1]);
            stage[n*136 + m + 8]     = __float2bfloat16(acc[f][j][2]);
            stage[(n+1)*136 + m + 8] = __float2bfloat16(acc[f][j][3]);
        }
    __syncthreads();
    #pragma unroll
    for (int it = 0; it < 8; it++) {
        int u = tid + it*256;
        int c = u >> 4, q = u & 15;
        uint4 val = *(const uint4*)&stage[c*136 + q*8];
        *(uint4*)&O[(((size_t)(b*256 + n0 + c))*HW + fix)*128 + q*8] = val;
    }
}

// ---------------- 10) bilinear upsample 127->256, residual ----------------
__global__ __launch_bounds__(256) void final_kernel(const float* __restrict__ x,
                                                    const float* __restrict__ gamma,
                                                    float* __restrict__ out) {
    int bc = blockIdx.z;
    int xx = blockIdx.x * 32 + (threadIdx.x & 31);
    int yy = blockIdx.y * 8  + (threadIdx.x >> 5);
    const float sc = 126.f / 255.f;
    float yf = yy * sc; int y0 = (int)yf; float wy = yf - y0; int y1 = min(y0+1, HW-1);
    float xf = xx * sc; int x0 = (int)xf; float wx = xf - x0; int x1 = min(x0+1, HW-1);
    const __nv_bfloat16* Ht = g_oH + (size_t)bc * HW * 128;   // [j][i]
    const __nv_bfloat16* Wt = g_oW + (size_t)bc * HW * 128;   // [i][j]
    float h00 = __bfloat162float(Ht[x0*128 + y0]), h01 = __bfloat162float(Ht[x0*128 + y1]);
    float h10 = __bfloat162float(Ht[x1*128 + y0]), h11 = __bfloat162float(Ht[x1*128 + y1]);
    float hv = (h00*(1.f-wy) + h01*wy)*(1.f-wx) + (h10*(1.f-wy) + h11*wy)*wx;
    float w00 = __bfloat162float(Wt[y0*128 + x0]), w01 = __bfloat162float(Wt[y0*128 + x1]);
    float w10 = __bfloat162float(Wt[y1*128 + x0]), w11 = __bfloat162float(Wt[y1*128 + x1]);
    float wv = (w00*(1.f-wx) + w01*wx)*(1.f-wy) + (w10*(1.f-wx) + w11*wx)*wy;
    size_t idx = (size_t)bc * IMGSZ + yy*IMG + xx;
    out[idx] = gamma[0] * (hv + wv) + x[idx];
}

// ---------------- launch ----------------
extern "C" void kernel_launch(void* const* d_in, const int* in_sizes, int n_in,
                              void* d_out, int out_size) {
    (void)in_sizes; (void)n_in; (void)out_size;
    const float* x  = (const float*)d_in[0];
    const float* am = (const float*)d_in[1];
    const float* wd = (const float*)d_in[2];
    const float* wq = (const float*)d_in[3];
    const float* bq = (const float*)d_in[4];
    const float* wk = (const float*)d_in[5];
    const float* bk = (const float*)d_in[6];
    const float* wv = (const float*)d_in[7];
    const float* bv = (const float*)d_in[8];
    const float* gm = (const float*)d_in[9];
    float* out = (float*)d_out;

    conv_down_kernel<<<(BB*CC*SSP + 255)/256, 256>>>(x, wd);
    xd_to_bf16_kernel<<<dim3(127, BB), 256>>>();
    resize_a_kernel<<<dim3(4, HW, BB), 256>>>(am);

    proj_qk_kernel<<<dim3(127, BB), 256>>>(wq, bq, wk, bk);
    proj_v_mma_kernel<<<dim3(127, 2, BB), 256>>>(wv, bv);
    vh_transpose_kernel<<<dim3(16, 8, BB), 256>>>();

    energy_kernel<32, false, true ><<<dim3(HW, BB), 256>>>();  // eH (masked)
    energy_kernel<32, true,  false><<<dim3(HW, BB), 256>>>();  // eW
    energy_kernel<64, false, true ><<<dim3(HW, BB), 256>>>();  // aH (masked)
    energy_kernel<64, true,  false><<<dim3(HW, BB), 256>>>();  // aW

    softmax3_kernel<<<(BB*SSP + 7)/8, 256>>>();

    outgemm_mma_kernel<false><<<dim3(HW, 2, BB), 256>>>();
    outgemm_mma_kernel<true ><<<dim3(HW, 2, BB), 256>>>();

    final_kernel<<<dim3(8, 32, BB*CC), 256>>>(x, gm, out);
}

// round 5
// speedup vs baseline: 1.1263x; 1.1263x over previous
#include <cuda_runtime.h>
#include <cuda_fp16.h>
#include <math.h>
#include <stdint.h>

#define SSP 16129   // 127*127
#define HW  127
#define BB  4
#define CC  256
#define IMG 256
#define IMGSZ 65536
#define ASP 132     // A smem row stride (floats)
#define NP2 130     // B smem row stride (float2, dup'd), even -> 16B aligned rows
#define NP2Q 66     // B stride for N=64 kernel

// ---------------- scratch (device globals; no allocation) ----------------
__device__ float g_xd[BB*CC*SSP];                    // downsampled x [b][c][s]
__device__ float g_qk[BB*SSP*64];                    // q(0..31)|k(32..63) [b][s][64]
__device__ float g_a [BB*SSP*64];                    // resized attn [b][s][64]
__device__ __align__(16) __half g_Eh[(size_t)BB*SSP*256];  // energies fp16 (rows of 256)
__device__ __align__(16) __half g_Ah[(size_t)BB*SSP*256];  // a-energies fp16
__device__ float g_S [(size_t)BB*SSP*256];           // softmax result fp32
__device__ float g_v [(size_t)BB*SSP*CC];            // v [b][s][256]
__device__ float g_oH[(size_t)BB*CC*HW*128];         // outH [b][c][j][i(pad128)]
__device__ float g_oW[(size_t)BB*CC*HW*128];         // outW [b][c][i][j(pad128)]

// ---------------- f32x2 helpers ----------------
__device__ __forceinline__ void fma2(unsigned long long& d, unsigned long long a, unsigned long long b) {
    asm("fma.rn.f32x2 %0, %1, %2, %0;" : "+l"(d) : "l"(a), "l"(b));
}
__device__ __forceinline__ float2 unpack2(unsigned long long v) {
    float2 r;
    asm("mov.b64 {%0, %1}, %2;" : "=f"(r.x), "=f"(r.y) : "l"(v));
    return r;
}

// 16-deep k step. As: [16][ASP] floats (m contiguous; thread owns m pairs
// (tx*4,tx*4+1),(tx*4+2,tx*4+3),(64+tx*4,..),(..)). Bs: [16][rs] float2 pre-duplicated.
// acc[p][n] accumulates (m_even*n, m_odd*n).
template<int NREG>
__device__ __forceinline__ void stepK16(const float* As, const float2* Bs,
                                        unsigned long long (*acc)[NREG], int tx, int ty) {
    const int rs = (NREG == 8) ? NP2 : NP2Q;
    #pragma unroll
    for (int kk = 0; kk < 16; kk++) {
        ulonglong2 a01 = *(const ulonglong2*)&As[kk*ASP + tx*4];
        ulonglong2 a23 = *(const ulonglong2*)&As[kk*ASP + 64 + tx*4];
        #pragma unroll
        for (int nb = 0; nb < NREG/2; nb++) {
            ulonglong2 bb = *(const ulonglong2*)&Bs[kk*rs + ty*NREG + nb*2];
            fma2(acc[0][nb*2],   a01.x, bb.x); fma2(acc[0][nb*2+1], a01.x, bb.y);
            fma2(acc[1][nb*2],   a01.y, bb.x); fma2(acc[1][nb*2+1], a01.y, bb.y);
            fma2(acc[2][nb*2],   a23.x, bb.x); fma2(acc[2][nb*2+1], a23.x, bb.y);
            fma2(acc[3][nb*2],   a23.y, bb.x); fma2(acc[3][nb*2+1], a23.y, bb.y);
        }
    }
}

// ---------------- 1) depthwise 4x4 stride-2 conv ----------------
__global__ void conv_down_kernel(const float* __restrict__ x, const float* __restrict__ wd) {
    int idx = blockIdx.x * blockDim.x + threadIdx.x;
    if (idx >= BB*CC*SSP) return;
    int j  = idx % HW;
    int i  = (idx / HW) % HW;
    int bc = idx / SSP;
    int c  = bc % CC;
    const float* px = x + (size_t)bc * IMGSZ + (2*i) * IMG + 2*j;
    const float* w  = wd + c * 16;
    float s = 0.f;
    #pragma unroll
    for (int dy = 0; dy < 4; dy++)
        #pragma unroll
        for (int dx = 0; dx < 4; dx++)
            s += px[dy*IMG + dx] * w[dy*4 + dx];
    g_xd[idx] = s;
}

// ---------------- 2) bilinear downsample of attention_map -> g_a [b][s][64] ----------------
__global__ __launch_bounds__(256) void resize_a_kernel(const float* __restrict__ am) {
    __shared__ float t[32][65];
    int b = blockIdx.z, i = blockIdx.y, j0 = blockIdx.x * 32;
    const float sc = 255.f / 126.f;
    float yf = i * sc; int y0 = (int)yf; float wy = yf - y0; int y1 = min(y0+1, IMG-1);
    #pragma unroll
    for (int it = 0; it < 8; it++) {
        int e = threadIdx.x + it*256;
        int ca = e >> 5, jj = e & 31;
        int j = j0 + jj;
        if (j < HW) {
            float xf = j * sc; int x0 = (int)xf; float wx = xf - x0; int x1 = min(x0+1, IMG-1);
            const float* P = am + ((size_t)(b*64 + ca)) * IMGSZ;
            float v = (P[y0*IMG+x0]*(1.f-wx) + P[y0*IMG+x1]*wx) * (1.f-wy)
                    + (P[y1*IMG+x0]*(1.f-wx) + P[y1*IMG+x1]*wx) * wy;
            t[jj][ca] = v;
        }
    }
    __syncthreads();
    #pragma unroll
    for (int it = 0; it < 8; it++) {
        int e = threadIdx.x + it*256;
        int jj = e >> 6, ca = e & 63;
        int j = j0 + jj;
        if (j < HW)
            g_a[((size_t)b*SSP + i*HW + j)*64 + ca] = t[jj][ca];
    }
}

// ---------------- 3) V projection (f32x2, pipelined) ----------------
__global__ __launch_bounds__(256) void proj_v_kernel(const float* __restrict__ W,
                                                     const float* __restrict__ bias) {
    extern __shared__ __align__(16) char dsm[];
    float*  As = (float*)dsm;                        // [2][16*ASP]
    float2* Bs = (float2*)(dsm + 2*16*ASP*4);        // [2][16*NP2]
    __shared__ float biass[128];
    int s0 = blockIdx.x*128, n0 = blockIdx.y*128, b = blockIdx.z;
    int tid = threadIdx.x, tx = tid&15, ty = tid>>4;
    const float* Xb = g_xd + (size_t)b*CC*SSP;
    unsigned long long acc[4][8] = {};
    float ar[8], br[8];
    if (tid < 128) biass[tid] = bias[n0 + tid];

    #define PV_LOAD(K0) { \
        _Pragma("unroll") \
        for (int i = 0; i < 8; i++) { \
            int e = tid + i*256, kk = e>>7, mm = e&127; \
            int s = s0 + mm; \
            ar[i] = (s < SSP) ? Xb[(size_t)((K0)+kk)*SSP + s] : 0.f; \
        } \
        _Pragma("unroll") \
        for (int i = 0; i < 8; i++) { \
            int e = tid + i*256, nn = e>>4, kk = e&15; \
            br[i] = W[(size_t)(n0+nn)*256 + (K0) + kk]; \
        } }
    #define PV_STORE(BUF) { \
        float* Ad = As + (BUF)*16*ASP; float2* Bd = Bs + (BUF)*16*NP2; \
        _Pragma("unroll") \
        for (int i = 0; i < 8; i++) { \
            int e = tid + i*256, kk = e>>7, mm = e&127; \
            Ad[kk*ASP + mm] = ar[i]; \
        } \
        _Pragma("unroll") \
        for (int i = 0; i < 8; i++) { \
            int e = tid + i*256, nn = e>>4, kk = e&15; \
            Bd[kk*NP2 + nn] = make_float2(br[i], br[i]); \
        } }

    PV_LOAD(0); PV_STORE(0);
    __syncthreads();
    for (int kt = 0; kt < 16; kt++) {
        if (kt < 15) PV_LOAD((kt+1)*16);
        stepK16<8>(As + (kt&1)*16*ASP, Bs + (kt&1)*16*NP2, acc, tx, ty);
        if (kt < 15) PV_STORE((kt+1)&1);
        __syncthreads();
    }
    #undef PV_LOAD
    #undef PV_STORE

    int nb = n0 + ty*8;
    #pragma unroll
    for (int mi = 0; mi < 8; mi++) {
        int p = mi>>1, h = mi&1;
        int s = s0 + ((mi<4) ? tx*4+mi : 64+tx*4+mi-4);
        if (s >= SSP) continue;
        float v[8];
        #pragma unroll
        for (int n = 0; n < 8; n++) {
            float2 t2 = unpack2(acc[p][n]);
            v[n] = (h ? t2.y : t2.x) + biass[ty*8+n];
        }
        float* o = g_v + ((size_t)b*SSP + s)*256 + nb;
        *(float4*)o     = make_float4(v[0],v[1],v[2],v[3]);
        *(float4*)(o+4) = make_float4(v[4],v[5],v[6],v[7]);
    }
}

// ---------------- 4) fused Q|K projection (f32x2, pipelined, N=64) ----------------
__global__ __launch_bounds__(256) void proj_qk_kernel(const float* __restrict__ wq, const float* __restrict__ bq,
                                                      const float* __restrict__ wk, const float* __restrict__ bk) {
    __shared__ __align__(16) float  As[2][16*ASP];
    __shared__ __align__(16) float2 Bs[2][16*NP2Q];
    int s0 = blockIdx.x*128, b = blockIdx.y;
    int tid = threadIdx.x, tx = tid&15, ty = tid>>4;
    const float* Xb = g_xd + (size_t)b*CC*SSP;
    unsigned long long acc[4][4] = {};
    float ar[8], br[4];

    #define QK_LOAD(K0) { \
        _Pragma("unroll") \
        for (int i = 0; i < 8; i++) { \
            int e = tid + i*256, kk = e>>7, mm = e&127; \
            int s = s0 + mm; \
            ar[i] = (s < SSP) ? Xb[(size_t)((K0)+kk)*SSP + s] : 0.f; \
        } \
        _Pragma("unroll") \
        for (int i = 0; i < 4; i++) { \
            int e = tid + i*256, nn = e>>4, kk = e&15; \
            br[i] = (nn < 32) ? wq[nn*256 + (K0) + kk] : wk[(nn-32)*256 + (K0) + kk]; \
        } }
    #define QK_STORE(BUF) { \
        _Pragma("unroll") \
        for (int i = 0; i < 8; i++) { \
            int e = tid + i*256, kk = e>>7, mm = e&127; \
            As[BUF][kk*ASP + mm] = ar[i]; \
        } \
        _Pragma("unroll") \
        for (int i = 0; i < 4; i++) { \
            int e = tid + i*256, nn = e>>4, kk = e&15; \
            Bs[BUF][kk*NP2Q + nn] = make_float2(br[i], br[i]); \
        } }

    QK_LOAD(0); QK_STORE(0);
    __syncthreads();
    for (int kt = 0; kt < 16; kt++) {
        if (kt < 15) QK_LOAD((kt+1)*16);
        stepK16<4>(&As[kt&1][0], &Bs[kt&1][0], acc, tx, ty);
        if (kt < 15) QK_STORE((kt+1)&1);
        __syncthreads();
    }
    #undef QK_LOAD
    #undef QK_STORE

    int nb = ty*4;
    float bv[4];
    #pragma unroll
    for (int ni = 0; ni < 4; ni++) {
        int n = nb + ni;
        bv[ni] = (n < 32) ? bq[n] : bk[n-32];
    }
    #pragma unroll
    for (int mi = 0; mi < 8; mi++) {
        int p = mi>>1, h = mi&1;
        int s = s0 + ((mi<4) ? tx*4+mi : 64+tx*4+mi-4);
        if (s >= SSP) continue;
        float v[4];
        #pragma unroll
        for (int n = 0; n < 4; n++) {
            float2 t2 = unpack2(acc[p][n]);
            v[n] = (h ? t2.y : t2.x) + bv[n];
        }
        *(float4*)&g_qk[((size_t)b*SSP + s)*64 + nb] = make_float4(v[0],v[1],v[2],v[3]);
    }
}

// ---------------- 5) energy GEMMs -> fp16 ----------------
// KDIM=32 -> qk -> g_Eh ; KDIM=64 -> a -> g_Ah
// MODEW=false (H): m=i, n=t, sp = idx*127+fix, diag mask, col offset 0
// MODEW=true  (W): m=p, n=t, sp = fix*127+idx, col offset 128
template<int KDIM, bool MODEW, bool MASK>
__global__ __launch_bounds__(256) void energy_kernel() {
    extern __shared__ __align__(16) char dsm[];
    float*  As = (float*)dsm;                    // [KDIM][ASP]
    float2* Bs = (float2*)(dsm + KDIM*ASP*4);    // [KDIM][NP2]
    const float* SRC = (KDIM==32) ? g_qk : g_a;
    __half* OUT      = (KDIM==32) ? g_Eh : g_Ah;
    const int qoff = 0, koff = (KDIM==32) ? 32 : 0;
    int fix = blockIdx.x, b = blockIdx.y;
    int tid = threadIdx.x, tx = tid&15, ty = tid>>4;
    const float* S = SRC + (size_t)b*SSP*64;
    const int NE = KDIM/2;      // elems per thread
    #pragma unroll
    for (int i = 0; i < NE; i++) {
        int e = tid + i*256;
        int kk = e & (KDIM-1), mm = e >> ((KDIM==32)?5:6);
        int sp = MODEW ? fix*HW + mm : mm*HW + fix;
        float qa = 0.f, kb = 0.f;
        if (mm < HW) {
            qa = S[(size_t)sp*64 + qoff + kk];
            kb = S[(size_t)sp*64 + koff + kk];
        }
        As[kk*ASP + mm] = qa;
        Bs[kk*NP2 + mm] = make_float2(kb, kb);
    }
    __syncthreads();
    unsigned long long acc[4][8] = {};
    #pragma unroll
    for (int kc = 0; kc < KDIM/16; kc++)
        stepK16<8>(As + kc*16*ASP, Bs + kc*16*NP2, acc, tx, ty);

    const int noff = MODEW ? 128 : 0;
    #pragma unroll
    for (int mi = 0; mi < 8; mi++) {
        int p = mi>>1, h = mi&1;
        int m = (mi<4) ? tx*4+mi : 64+tx*4+mi-4;
        if (m >= HW) continue;
        size_t row = MODEW ? ((size_t)(b*HW+fix)*HW + m) : ((size_t)(b*HW+m)*HW + fix);
        float v[8];
        #pragma unroll
        for (int n = 0; n < 8; n++) {
            float2 t2 = unpack2(acc[p][n]);
            v[n] = h ? t2.y : t2.x;
        }
        #pragma unroll
        for (int n = 0; n < 8; n++) {
            int nn = ty*8 + n;
            if (nn == HW) v[n] = -INFINITY;
            if (MASK && nn == m) v[n] = -INFINITY;
        }
        __half2 q0 = __floats2half2_rn(v[0], v[1]);
        __half2 q1 = __floats2half2_rn(v[2], v[3]);
        __half2 q2 = __floats2half2_rn(v[4], v[5]);
        __half2 q3 = __floats2half2_rn(v[6], v[7]);
        uint4 u = make_uint4(*(uint32_t*)&q0, *(uint32_t*)&q1, *(uint32_t*)&q2, *(uint32_t*)&q3);
        *(uint4*)&OUT[row*256 + noff + ty*8] = u;
    }
}

// ---------------- 6) fused triple softmax (fp16 in, fp32 out) ----------------
__device__ __forceinline__ float wmax(float v) {
    #pragma unroll
    for (int o = 16; o; o >>= 1) v = fmaxf(v, __shfl_xor_sync(0xffffffffu, v, o));
    return v;
}
__device__ __forceinline__ float wsum(float v) {
    #pragma unroll
    for (int o = 16; o; o >>= 1) v += __shfl_xor_sync(0xffffffffu, v, o);
    return v;
}
__global__ __launch_bounds__(256) void softmax3_kernel() {
    int w = threadIdx.x >> 5, lane = threadIdx.x & 31;
    size_t row = (size_t)blockIdx.x * 8 + w;
    if (row >= (size_t)BB*SSP) return;
    uint4 eu = ((const uint4*)(g_Eh + row*256))[lane];
    uint4 au = ((const uint4*)(g_Ah + row*256))[lane];
    float ev[8], av[8];
    const __half2* ep = (const __half2*)&eu;
    const __half2* ap = (const __half2*)&au;
    #pragma unroll
    for (int i = 0; i < 4; i++) {
        float2 f = __half22float2(ep[i]); ev[2*i] = f.x; ev[2*i+1] = f.y;
        float2 g = __half22float2(ap[i]); av[2*i] = g.x; av[2*i+1] = g.y;
    }
    float m1 = -INFINITY, m2 = -INFINITY;
    #pragma unroll
    for (int i = 0; i < 8; i++) { m1 = fmaxf(m1, ev[i]); m2 = fmaxf(m2, av[i]); }
    m1 = wmax(m1); m2 = wmax(m2);
    float ce[8], ca[8], s1 = 0.f, s2 = 0.f;
    #pragma unroll
    for (int i = 0; i < 8; i++) {
        ce[i] = __expf(ev[i] - m1); s1 += ce[i];
        ca[i] = __expf(av[i] - m2); s2 += ca[i];
    }
    s1 = wsum(s1); s2 = wsum(s2);
    float r12 = 1.f / (s1 * s2);
    float pv[8];
    #pragma unroll
    for (int i = 0; i < 8; i++) pv[i] = ce[i] * ca[i] * r12;
    if (lane == 15 || lane == 31) pv[7] = -INFINITY;   // pad slots 127 / 255
    float m3 = -INFINITY;
    #pragma unroll
    for (int i = 0; i < 8; i++) m3 = fmaxf(m3, pv[i]);
    m3 = wmax(m3);
    float s3 = 0.f, ov[8];
    #pragma unroll
    for (int i = 0; i < 8; i++) { ov[i] = __expf(pv[i] - m3); s3 += ov[i]; }
    s3 = wsum(s3);
    float r3 = 1.f / s3;
    float* Sr = g_S + row*256;
    ((float4*)Sr)[lane*2]   = make_float4(ov[0]*r3, ov[1]*r3, ov[2]*r3, ov[3]*r3);
    ((float4*)Sr)[lane*2+1] = make_float4(ov[4]*r3, ov[5]*r3, ov[6]*r3, ov[7]*r3);
}

// ---------------- 7) out GEMMs (f32x2, pipelined) ----------------
// MODEW=false (H): per (b,j=fix): D[c][i] = sum_l S[b,i,fix][l] * v[b,l*127+fix,c] -> oH[b][c][fix][i]
// MODEW=true  (W): per (b,i=fix): D[c][j] = sum_u S[b,fix,j][128+u] * v[b,fix*127+u,c] -> oW[b][c][fix][j]
template<bool MODEW>
__global__ __launch_bounds__(256) void outgemm_kernel() {
    extern __shared__ __align__(16) char dsm[];
    float*  As = (float*)dsm;                    // [2][16*ASP] : v (m=c)
    float2* Bs = (float2*)(dsm + 2*16*ASP*4);    // [2][16*NP2] : S (n=t, dup)
    int fix = blockIdx.x, c0 = blockIdx.y*128, b = blockIdx.z;
    int tid = threadIdx.x, tx = tid&15, ty = tid>>4;
    const int noff = MODEW ? 128 : 0;
    unsigned long long acc[4][8] = {};
    float ar[8], br[8];

    #define OG_LOAD(K0) { \
        _Pragma("unroll") \
        for (int i = 0; i < 8; i++) { \
            int e = tid + i*256, kk = e>>7, mm = e&127; \
            int k = (K0) + kk; \
            int sp = MODEW ? fix*HW + k : k*HW + fix; \
            ar[i] = (k < HW) ? g_v[((size_t)b*SSP + sp)*256 + c0 + mm] : 0.f; \
        } \
        _Pragma("unroll") \
        for (int i = 0; i < 8; i++) { \
            int e = tid + i*256, nn = e>>4, kk = e&15; \
            size_t srow = MODEW ? ((size_t)(b*HW+fix)*HW + nn) : ((size_t)(b*HW+nn)*HW + fix); \
            br[i] = (nn < HW) ? g_S[srow*256 + noff + (K0) + kk] : 0.f; \
        } }
    #define OG_STORE(BUF) { \
        float* Ad = As + (BUF)*16*ASP; float2* Bd = Bs + (BUF)*16*NP2; \
        _Pragma("unroll") \
        for (int i = 0; i < 8; i++) { \
            int e = tid + i*256, kk = e>>7, mm = e&127; \
            Ad[kk*ASP + mm] = ar[i]; \
        } \
        _Pragma("unroll") \
        for (int i = 0; i < 8; i++) { \
            int e = tid + i*256, nn = e>>4, kk = e&15; \
            Bd[kk*NP2 + nn] = make_float2(br[i], br[i]); \
        } }

    OG_LOAD(0); OG_STORE(0);
    __syncthreads();
    for (int kt = 0; kt < 8; kt++) {
        if (kt < 7) OG_LOAD((kt+1)*16);
        stepK16<8>(As + (kt&1)*16*ASP, Bs + (kt&1)*16*NP2, acc, tx, ty);
        if (kt < 7) OG_STORE((kt+1)&1);
        __syncthreads();
    }
    #undef OG_LOAD
    #undef OG_STORE

    float* O = MODEW ? g_oW : g_oH;
    #pragma unroll
    for (int mi = 0; mi < 8; mi++) {
        int p = mi>>1, h = mi&1;
        int c = c0 + ((mi<4) ? tx*4+mi : 64+tx*4+mi-4);
        float v[8];
        #pragma unroll
        for (int n = 0; n < 8; n++) {
            float2 t2 = unpack2(acc[p][n]);
            v[n] = h ? t2.y : t2.x;
        }
        float* o = O + ((size_t)(b*256 + c)*HW + fix)*128 + ty*8;
        *(float4*)o     = make_float4(v[0],v[1],v[2],v[3]);
        *(float4*)(o+4) = make_float4(v[4],v[5],v[6],v[7]);
    }
}

// ---------------- 8) bilinear upsample 127->256, residual ----------------
__global__ __launch_bounds__(256) void final_kernel(const float* __restrict__ x,
                                                    const float* __restrict__ gamma,
                                                    float* __restrict__ out) {
    int bc = blockIdx.z;
    int xx = blockIdx.x * 32 + (threadIdx.x & 31);
    int yy = blockIdx.y * 8  + (threadIdx.x >> 5);
    const float sc = 126.f / 255.f;
    float yf = yy * sc; int y0 = (int)yf; float wy = yf - y0; int y1 = min(y0+1, HW-1);
    float xf = xx * sc; int x0 = (int)xf; float wx = xf - x0; int x1 = min(x0+1, HW-1);
    const float* Ht = g_oH + (size_t)bc * HW * 128;   // [j][i]
    const float* Wt = g_oW + (size_t)bc * HW * 128;   // [i][j]
    float h00 = Ht[x0*128 + y0], h01 = Ht[x0*128 + y1];
    float h10 = Ht[x1*128 + y0], h11 = Ht[x1*128 + y1];
    float hv = (h00*(1.f-wy) + h01*wy)*(1.f-wx) + (h10*(1.f-wy) + h11*wy)*wx;
    float w00 = Wt[y0*128 + x0], w01 = Wt[y0*128 + x1];
    float w10 = Wt[y1*128 + x0], w11 = Wt[y1*128 + x1];
    float wv = (w00*(1.f-wx) + w01*wx)*(1.f-wy) + (w10*(1.f-wx) + w11*wx)*wy;
    size_t idx = (size_t)bc * IMGSZ + yy*IMG + xx;
    out[idx] = gamma[0] * (hv + wv) + x[idx];
}

// ---------------- launch ----------------
extern "C" void kernel_launch(void* const* d_in, const int* in_sizes, int n_in,
                              void* d_out, int out_size) {
    (void)in_sizes; (void)n_in; (void)out_size;
    const float* x  = (const float*)d_in[0];
    const float* am = (const float*)d_in[1];
    const float* wd = (const float*)d_in[2];
    const float* wq = (const float*)d_in[3];
    const float* bq = (const float*)d_in[4];
    const float* wk = (const float*)d_in[5];
    const float* bk = (const float*)d_in[6];
    const float* wv = (const float*)d_in[7];
    const float* bv = (const float*)d_in[8];
    const float* gm = (const float*)d_in[9];
    float* out = (float*)d_out;

    const int SM_PIPE = 2*16*ASP*4 + 2*16*NP2*8;   // 50176
    const int SM_E32  = 32*ASP*4 + 32*NP2*8;       // 50176
    const int SM_E64  = 64*ASP*4 + 64*NP2*8;       // 100352

    cudaFuncSetAttribute(proj_v_kernel, cudaFuncAttributeMaxDynamicSharedMemorySize, SM_PIPE);
    cudaFuncSetAttribute(outgemm_kernel<false>, cudaFuncAttributeMaxDynamicSharedMemorySize, SM_PIPE);
    cudaFuncSetAttribute(outgemm_kernel<true>,  cudaFuncAttributeMaxDynamicSharedMemorySize, SM_PIPE);
    cudaFuncSetAttribute(energy_kernel<32,false,true>,  cudaFuncAttributeMaxDynamicSharedMemorySize, SM_E32);
    cudaFuncSetAttribute(energy_kernel<32,true,false>,  cudaFuncAttributeMaxDynamicSharedMemorySize, SM_E32);
    cudaFuncSetAttribute(energy_kernel<64,false,true>,  cudaFuncAttributeMaxDynamicSharedMemorySize, SM_E64);
    cudaFuncSetAttribute(energy_kernel<64,true,false>,  cudaFuncAttributeMaxDynamicSharedMemorySize, SM_E64);

    conv_down_kernel<<<(BB*CC*SSP + 255)/256, 256>>>(x, wd);
    resize_a_kernel<<<dim3(4, HW, BB), 256>>>(am);

    proj_qk_kernel<<<dim3(127, BB), 256>>>(wq, bq, wk, bk);
    proj_v_kernel<<<dim3(127, 2, BB), 256, SM_PIPE>>>(wv, bv);

    energy_kernel<32, false, true ><<<dim3(HW, BB), 256, SM_E32>>>();  // eH (masked)
    energy_kernel<32, true,  false><<<dim3(HW, BB), 256, SM_E32>>>();  // eW
    energy_kernel<64, false, true ><<<dim3(HW, BB), 256, SM_E64>>>();  // aH (masked)
    energy_kernel<64, true,  false><<<dim3(HW, BB), 256, SM_E64>>>();  // aW

    softmax3_kernel<<<(BB*SSP + 7)/8, 256>>>();

    outgemm_kernel<false><<<dim3(HW, 2, BB), 256, SM_PIPE>>>();
    outgemm_kernel<true ><<<dim3(HW, 2, BB), 256, SM_PIPE>>>();

    final_kernel<<<dim3(8, 32, BB*CC), 256>>>(x, gm, out);
}

// round 7
// speedup vs baseline: 1.2279x; 1.0902x over previous
#include <cuda_runtime.h>
#include <cuda_fp16.h>
#include <math.h>
#include <stdint.h>

#define SSP 16129   // 127*127
#define XDP 16132   // padded xd row stride (multiple of 4 -> 16B-aligned rows)
#define HW  127
#define BB  4
#define CC  256
#define IMG 256
#define IMGSZ 65536
#define ASP 132     // A smem row stride (floats)
#define NP2 130     // B smem row stride (float2, pre-duplicated)
#define NP2Q 66     // B stride for N=64 kernel

// ---------------- scratch (device globals; no allocation) ----------------
__device__ __align__(16) float g_xd[(size_t)BB*CC*XDP];    // downsampled x [b][c][s(pad)]
__device__ float g_qk[BB*SSP*64];                    // q(0..31)|k(32..63) [b][s][64]
__device__ float g_a [BB*SSP*64];                    // resized attn [b][s][64]
__device__ __align__(16) __half g_Eh[(size_t)BB*SSP*256];  // energies fp16 (rows of 256)
__device__ __align__(16) __half g_Ah[(size_t)BB*SSP*256];  // a-energies fp16
__device__ float g_S [(size_t)BB*SSP*256];           // softmax result fp32
__device__ __align__(16) float g_v [(size_t)BB*SSP*CC];    // v [b][s][256]
__device__ __align__(16) __half g_oH[(size_t)BB*CC*HW*128]; // outH [b][c][j][i(pad128)]
__device__ __align__(16) __half g_oW[(size_t)BB*CC*HW*128]; // outW [b][c][i][j(pad128)]

// ---------------- helpers ----------------
__device__ __forceinline__ uint32_t smem_u32(const void* p) {
    uint32_t a;
    asm("{ .reg .u64 t; cvta.to.shared.u64 t, %1; cvt.u32.u64 %0, t; }" : "=r"(a) : "l"(p));
    return a;
}
__device__ __forceinline__ unsigned long long dup2(float x) {
    unsigned long long r;
    asm("mov.b64 %0, {%1, %1};" : "=l"(r) : "f"(x));
    return r;
}
__device__ __forceinline__ void fma2(unsigned long long& d, unsigned long long a, unsigned long long b) {
    asm("fma.rn.f32x2 %0, %1, %2, %0;" : "+l"(d) : "l"(a), "l"(b));
}
__device__ __forceinline__ float2 unpack2(unsigned long long v) {
    float2 r;
    asm("mov.b64 {%0, %1}, %2;" : "=f"(r.x), "=f"(r.y) : "l"(v));
    return r;
}
#define CP_ASYNC16(dst, src, nb) \
    asm volatile("cp.async.cg.shared.global [%0], [%1], 16, %2;" :: "r"(dst), "l"(src), "r"(nb))
#define CP_COMMIT asm volatile("cp.async.commit_group;" ::: "memory")
#define CP_WAIT0  asm volatile("cp.async.wait_group 0;" ::: "memory")

// m-paired microkernel: As [16][ASP] floats (m contiguous); Bs [16][rs] float2 pre-dup.
// thread owns m pairs (tx*4,tx*4+1),(tx*4+2,+3),(64+tx*4,..),(..); n = ty*NREG..+NREG-1.
template<int NREG>
__device__ __forceinline__ void stepK16(const float* As, const float2* Bs,
                                        unsigned long long (*acc)[NREG], int tx, int ty) {
    const int rs = (NREG == 8) ? NP2 : NP2Q;
    #pragma unroll
    for (int kk = 0; kk < 16; kk++) {
        ulonglong2 a01 = *(const ulonglong2*)&As[kk*ASP + tx*4];
        ulonglong2 a23 = *(const ulonglong2*)&As[kk*ASP + 64 + tx*4];
        #pragma unroll
        for (int nb = 0; nb < NREG/2; nb++) {
            ulonglong2 bb = *(const ulonglong2*)&Bs[kk*rs + ty*NREG + nb*2];
            fma2(acc[0][nb*2],   a01.x, bb.x); fma2(acc[0][nb*2+1], a01.x, bb.y);
            fma2(acc[1][nb*2],   a01.y, bb.x); fma2(acc[1][nb*2+1], a01.y, bb.y);
            fma2(acc[2][nb*2],   a23.x, bb.x); fma2(acc[2][nb*2+1], a23.x, bb.y);
            fma2(acc[3][nb*2],   a23.y, bb.x); fma2(acc[3][nb*2+1], a23.y, bb.y);
        }
    }
}

// R2-style broadcast microkernel (for energies): As/Bs [16][132] floats.
__device__ __forceinline__ void micro128(const float* As, const float* Bs,
                                         unsigned long long acc[8][4], int tx, int ty) {
    #pragma unroll
    for (int kk = 0; kk < 16; kk++) {
        float4 x0 = *(const float4*)&As[kk*132 + tx*4];
        float4 x1 = *(const float4*)&As[kk*132 + 64 + tx*4];
        ulonglong2 w0 = *(const ulonglong2*)&Bs[kk*132 + ty*8];
        ulonglong2 w1 = *(const ulonglong2*)&Bs[kk*132 + ty*8 + 4];
        unsigned long long xs[8];
        xs[0]=dup2(x0.x); xs[1]=dup2(x0.y); xs[2]=dup2(x0.z); xs[3]=dup2(x0.w);
        xs[4]=dup2(x1.x); xs[5]=dup2(x1.y); xs[6]=dup2(x1.z); xs[7]=dup2(x1.w);
        #pragma unroll
        for (int m = 0; m < 8; m++) {
            fma2(acc[m][0], xs[m], w0.x);
            fma2(acc[m][1], xs[m], w0.y);
            fma2(acc[m][2], xs[m], w1.x);
            fma2(acc[m][3], xs[m], w1.y);
        }
    }
}

// ---------------- 1) depthwise 4x4 stride-2 conv ----------------
__global__ void conv_down_kernel(const float* __restrict__ x, const float* __restrict__ wd) {
    int idx = blockIdx.x * blockDim.x + threadIdx.x;
    if (idx >= BB*CC*SSP) return;
    int j  = idx % HW;
    int i  = (idx / HW) % HW;
    int bc = idx / SSP;
    int c  = bc % CC;
    const float* px = x + (size_t)bc * IMGSZ + (2*i) * IMG + 2*j;
    const float* w  = wd + c * 16;
    float s = 0.f;
    #pragma unroll
    for (int dy = 0; dy < 4; dy++)
        #pragma unroll
        for (int dx = 0; dx < 4; dx++)
            s += px[dy*IMG + dx] * w[dy*4 + dx];
    g_xd[(size_t)bc*XDP + i*HW + j] = s;
}

// ---------------- 2) bilinear downsample of attention_map -> g_a [b][s][64] ----------------
__global__ __launch_bounds__(256) void resize_a_kernel(const float* __restrict__ am) {
    __shared__ float t[32][65];
    int b = blockIdx.z, i = blockIdx.y, j0 = blockIdx.x * 32;
    const float sc = 255.f / 126.f;
    float yf = i * sc; int y0 = (int)yf; float wy = yf - y0; int y1 = min(y0+1, IMG-1);
    #pragma unroll
    for (int it = 0; it < 8; it++) {
        int e = threadIdx.x + it*256;
        int ca = e >> 5, jj = e & 31;
        int j = j0 + jj;
        if (j < HW) {
            float xf = j * sc; int x0 = (int)xf; float wx = xf - x0; int x1 = min(x0+1, IMG-1);
            const float* P = am + ((size_t)(b*64 + ca)) * IMGSZ;
            float v = (P[y0*IMG+x0]*(1.f-wx) + P[y0*IMG+x1]*wx) * (1.f-wy)
                    + (P[y1*IMG+x0]*(1.f-wx) + P[y1*IMG+x1]*wx) * wy;
            t[jj][ca] = v;
        }
    }
    __syncthreads();
    #pragma unroll
    for (int it = 0; it < 8; it++) {
        int e = threadIdx.x + it*256;
        int jj = e >> 6, ca = e & 63;
        int j = j0 + jj;
        if (j < HW)
            g_a[((size_t)b*SSP + i*HW + j)*64 + ca] = t[jj][ca];
    }
}

// ---------------- 3) V projection (f32x2, cp.async double-buffered) ----------------
__global__ __launch_bounds__(256, 2) void proj_v_kernel(const float* __restrict__ W,
                                                        const float* __restrict__ bias) {
    extern __shared__ __align__(16) char dsm[];
    float*  As = (float*)dsm;                        // [2][16*ASP]
    float2* Bs = (float2*)(dsm + 2*16*ASP*4);        // [2][16*NP2]
    __shared__ float biass[128];
    int s0 = blockIdx.x*128, n0 = blockIdx.y*128, b = blockIdx.z;
    int tid = threadIdx.x, tx = tid&15, ty = tid>>4;
    const float* Xb = g_xd + (size_t)b*CC*XDP;
    unsigned long long acc[4][8] = {};
    float br[8];
    if (tid < 128) biass[tid] = bias[n0 + tid];
    uint32_t a_smem = smem_u32(As);

    #define PV_AISSUE(K0, BUF) { \
        _Pragma("unroll") \
        for (int i = 0; i < 2; i++) { \
            int e = tid + i*256; \
            int kk = e >> 5, m4 = e & 31; \
            int s = s0 + m4*4; \
            const float* src = &Xb[(size_t)((K0)+kk)*XDP + s]; \
            int nb = (SSP - s)*4; nb = nb < 0 ? 0 : (nb > 16 ? 16 : nb); \
            if (nb == 0) src = Xb; \
            uint32_t dst = a_smem + ((BUF)*16*ASP + kk*ASP + m4*4)*4; \
            CP_ASYNC16(dst, src, nb); \
        } }
    #define PV_BLOAD(K0) { \
        _Pragma("unroll") \
        for (int i = 0; i < 8; i++) { \
            int e = tid + i*256; int nn = e>>4, kk = e&15; \
            br[i] = W[(size_t)(n0+nn)*256 + (K0) + kk]; \
        } }
    #define PV_BSTORE(BUF) { \
        _Pragma("unroll") \
        for (int i = 0; i < 8; i++) { \
            int e = tid + i*256; int nn = e>>4, kk = e&15; \
            Bs[(BUF)*16*NP2 + kk*NP2 + nn] = make_float2(br[i], br[i]); \
        } }

    PV_AISSUE(0, 0); CP_COMMIT;
    PV_BLOAD(0); PV_BSTORE(0);
    CP_WAIT0; __syncthreads();
    for (int kt = 0; kt < 16; kt++) {
        if (kt < 15) { PV_AISSUE((kt+1)*16, (kt+1)&1); CP_COMMIT; PV_BLOAD((kt+1)*16); }
        stepK16<8>(As + (kt&1)*16*ASP, Bs + (kt&1)*16*NP2, acc, tx, ty);
        if (kt < 15) { PV_BSTORE((kt+1)&1); CP_WAIT0; }
        __syncthreads();
    }
    #undef PV_AISSUE
    #undef PV_BLOAD
    #undef PV_BSTORE

    int nb = n0 + ty*8;
    #pragma unroll
    for (int mi = 0; mi < 8; mi++) {
        int p = mi>>1, h = mi&1;
        int s = s0 + ((mi<4) ? tx*4+mi : 64+tx*4+mi-4);
        if (s >= SSP) continue;
        float v[8];
        #pragma unroll
        for (int n = 0; n < 8; n++) {
            float2 t2 = unpack2(acc[p][n]);
            v[n] = (h ? t2.y : t2.x) + biass[ty*8+n];
        }
        float* o = g_v + ((size_t)b*SSP + s)*256 + nb;
        *(float4*)o     = make_float4(v[0],v[1],v[2],v[3]);
        *(float4*)(o+4) = make_float4(v[4],v[5],v[6],v[7]);
    }
}

// ---------------- 4) fused Q|K projection (f32x2, cp.async, N=64) ----------------
__global__ __launch_bounds__(256, 2) void proj_qk_kernel(const float* __restrict__ wq, const float* __restrict__ bq,
                                                         const float* __restrict__ wk, const float* __restrict__ bk) {
    __shared__ __align__(16) float  As[2][16*ASP];
    __shared__ __align__(16) float2 Bs[2][16*NP2Q];
    int s0 = blockIdx.x*128, b = blockIdx.y;
    int tid = threadIdx.x, tx = tid&15, ty = tid>>4;
    const float* Xb = g_xd + (size_t)b*CC*XDP;
    unsigned long long acc[4][4] = {};
    float br[4];
    uint32_t a_smem = smem_u32(&As[0][0]);

    #define QK_AISSUE(K0, BUF) { \
        _Pragma("unroll") \
        for (int i = 0; i < 2; i++) { \
            int e = tid + i*256; \
            int kk = e >> 5, m4 = e & 31; \
            int s = s0 + m4*4; \
            const float* src = &Xb[(size_t)((K0)+kk)*XDP + s]; \
            int nb = (SSP - s)*4; nb = nb < 0 ? 0 : (nb > 16 ? 16 : nb); \
            if (nb == 0) src = Xb; \
            uint32_t dst = a_smem + ((BUF)*16*ASP + kk*ASP + m4*4)*4; \
            CP_ASYNC16(dst, src, nb); \
        } }
    #define QK_BLOAD(K0) { \
        _Pragma("unroll") \
        for (int i = 0; i < 4; i++) { \
            int e = tid + i*256; int nn = e>>4, kk = e&15; \
            br[i] = (nn < 32) ? wq[nn*256 + (K0) + kk] : wk[(nn-32)*256 + (K0) + kk]; \
        } }
    #define QK_BSTORE(BUF) { \
        _Pragma("unroll") \
        for (int i = 0; i < 4; i++) { \
            int e = tid + i*256; int nn = e>>4, kk = e&15; \
            Bs[BUF][kk*NP2Q + nn] = make_float2(br[i], br[i]); \
        } }

    QK_AISSUE(0, 0); CP_COMMIT;
    QK_BLOAD(0); QK_BSTORE(0);
    CP_WAIT0; __syncthreads();
    for (int kt = 0; kt < 16; kt++) {
        if (kt < 15) { QK_AISSUE((kt+1)*16, (kt+1)&1); CP_COMMIT; QK_BLOAD((kt+1)*16); }
        stepK16<4>(&As[kt&1][0], &Bs[kt&1][0], acc, tx, ty);
        if (kt < 15) { QK_BSTORE((kt+1)&1); CP_WAIT0; }
        __syncthreads();
    }
    #undef QK_AISSUE
    #undef QK_BLOAD
    #undef QK_BSTORE

    int nb = ty*4;
    float bv[4];
    #pragma unroll
    for (int ni = 0; ni < 4; ni++) {
        int n = nb + ni;
        bv[ni] = (n < 32) ? bq[n] : bk[n-32];
    }
    #pragma unroll
    for (int mi = 0; mi < 8; mi++) {
        int p = mi>>1, h = mi&1;
        int s = s0 + ((mi<4) ? tx*4+mi : 64+tx*4+mi-4);
        if (s >= SSP) continue;
        float v[4];
        #pragma unroll
        for (int n = 0; n < 4; n++) {
            float2 t2 = unpack2(acc[p][n]);
            v[n] = (h ? t2.y : t2.x) + bv[n];
        }
        *(float4*)&g_qk[((size_t)b*SSP + s)*64 + nb] = make_float4(v[0],v[1],v[2],v[3]);
    }
}

// ---------------- 5) energy GEMMs (R2 structure) -> fp16 ----------------
// KDIM=32 -> qk -> g_Eh ; KDIM=64 -> a -> g_Ah
template<int KDIM, bool MODEW, bool MASK>
__global__ __launch_bounds__(256) void energy_kernel() {
    __shared__ __align__(16) float As[16*132];
    __shared__ __align__(16) float Bs[16*132];
    const float* SRC = (KDIM==32) ? g_qk : g_a;
    __half* OUT      = (KDIM==32) ? g_Eh : g_Ah;
    const int qoff = 0, koff = (KDIM==32) ? 32 : 0;
    int fix = blockIdx.x, b = blockIdx.y;
    int tid = threadIdx.x, tx = tid&15, ty = tid>>4;
    unsigned long long acc[8][4] = {};
    const float* S = SRC + (size_t)b*SSP*64;
    #pragma unroll
    for (int k0 = 0; k0 < KDIM; k0 += 16) {
        #pragma unroll
        for (int i = 0; i < 8; i++) {
            int e = tid + i*256;
            int mm = e >> 4, kk = e & 15;
            int sp = MODEW ? fix*HW + mm : mm*HW + fix;
            float qa = 0.f, kb = 0.f;
            if (mm < HW) {
                qa = S[(size_t)sp*64 + qoff + k0 + kk];
                kb = S[(size_t)sp*64 + koff + k0 + kk];
            }
            As[kk*132 + mm] = qa;
            Bs[kk*132 + mm] = kb;
        }
        __syncthreads();
        micro128(As, Bs, acc, tx, ty);
        __syncthreads();
    }
    const int noff = MODEW ? 128 : 0;
    #pragma unroll
    for (int mi = 0; mi < 8; mi++) {
        int m = (mi < 4) ? tx*4 + mi : 64 + tx*4 + mi - 4;
        if (m >= HW) continue;
        size_t row = MODEW ? ((size_t)(b*HW + fix)*HW + m) : ((size_t)(b*HW + m)*HW + fix);
        float v[8];
        #pragma unroll
        for (int np = 0; np < 4; np++) {
            float2 p = unpack2(acc[mi][np]);
            v[np*2] = p.x; v[np*2+1] = p.y;
        }
        #pragma unroll
        for (int ni = 0; ni < 8; ni++) {
            int n = ty*8 + ni;
            if (n == HW) v[ni] = -INFINITY;
            if (MASK && n == m) v[ni] = -INFINITY;
        }
        __half2 q0 = __floats2half2_rn(v[0], v[1]);
        __half2 q1 = __floats2half2_rn(v[2], v[3]);
        __half2 q2 = __floats2half2_rn(v[4], v[5]);
        __half2 q3 = __floats2half2_rn(v[6], v[7]);
        uint4 u = make_uint4(*(uint32_t*)&q0, *(uint32_t*)&q1, *(uint32_t*)&q2, *(uint32_t*)&q3);
        *(uint4*)&OUT[row*256 + noff + ty*8] = u;
    }
}

// ---------------- 6) fused triple softmax (fp16 in, fp32 out) ----------------
__device__ __forceinline__ float wmax(float v) {
    #pragma unroll
    for (int o = 16; o; o >>= 1) v = fmaxf(v, __shfl_xor_sync(0xffffffffu, v, o));
    return v;
}
__device__ __forceinline__ float wsum(float v) {
    #pragma unroll
    for (int o = 16; o; o >>= 1) v += __shfl_xor_sync(0xffffffffu, v, o);
    return v;
}
__global__ __launch_bounds__(256) void softmax3_kernel() {
    int w = threadIdx.x >> 5, lane = threadIdx.x & 31;
    size_t row = (size_t)blockIdx.x * 8 + w;
    if (row >= (size_t)BB*SSP) return;
    uint4 eu = ((const uint4*)(g_Eh + row*256))[lane];
    uint4 au = ((const uint4*)(g_Ah + row*256))[lane];
    float ev[8], av[8];
    const __half2* ep = (const __half2*)&eu;
    const __half2* ap = (const __half2*)&au;
    #pragma unroll
    for (int i = 0; i < 4; i++) {
        float2 f = __half22float2(ep[i]); ev[2*i] = f.x; ev[2*i+1] = f.y;
        float2 g = __half22float2(ap[i]); av[2*i] = g.x; av[2*i+1] = g.y;
    }
    float m1 = -INFINITY, m2 = -INFINITY;
    #pragma unroll
    for (int i = 0; i < 8; i++) { m1 = fmaxf(m1, ev[i]); m2 = fmaxf(m2, av[i]); }
    m1 = wmax(m1); m2 = wmax(m2);
    float ce[8], ca[8], s1 = 0.f, s2 = 0.f;
    #pragma unroll
    for (int i = 0; i < 8; i++) {
        ce[i] = __expf(ev[i] - m1); s1 += ce[i];
        ca[i] = __expf(av[i] - m2); s2 += ca[i];
    }
    s1 = wsum(s1); s2 = wsum(s2);
    float r12 = 1.f / (s1 * s2);
    float pv[8];
    #pragma unroll
    for (int i = 0; i < 8; i++) pv[i] = ce[i] * ca[i] * r12;
    if (lane == 15 || lane == 31) pv[7] = -INFINITY;   // pad slots 127 / 255
    float m3 = -INFINITY;
    #pragma unroll
    for (int i = 0; i < 8; i++) m3 = fmaxf(m3, pv[i]);
    m3 = wmax(m3);
    float s3 = 0.f, ov[8];
    #pragma unroll
    for (int i = 0; i < 8; i++) { ov[i] = __expf(pv[i] - m3); s3 += ov[i]; }
    s3 = wsum(s3);
    float r3 = 1.f / s3;
    float* Sr = g_S + row*256;
    ((float4*)Sr)[lane*2]   = make_float4(ov[0]*r3, ov[1]*r3, ov[2]*r3, ov[3]*r3);
    ((float4*)Sr)[lane*2+1] = make_float4(ov[4]*r3, ov[5]*r3, ov[6]*r3, ov[7]*r3);
}

// ---------------- 7) out GEMMs (f32x2, cp.async double-buffered) -> fp16 ----------------
// MODEW=false (H): per (b,j=fix): D[c][i] = sum_l S[b,i,fix][l] * v[b,l*127+fix,c] -> oH[b][c][fix][i]
// MODEW=true  (W): per (b,i=fix): D[c][j] = sum_u S[b,fix,j][128+u] * v[b,fix*127+u,c] -> oW[b][c][fix][j]
template<bool MODEW>
__global__ __launch_bounds__(256, 2) void outgemm_kernel() {
    extern __shared__ __align__(16) char dsm[];
    float*  As = (float*)dsm;                    // [2][16*ASP] : v (m=c)
    float2* Bs = (float2*)(dsm + 2*16*ASP*4);    // [2][16*NP2] : S (n, dup)
    int fix = blockIdx.x, c0 = blockIdx.y*128, b = blockIdx.z;
    int tid = threadIdx.x, tx = tid&15, ty = tid>>4;
    const int noff = MODEW ? 128 : 0;
    unsigned long long acc[4][8] = {};
    float br[8];
    uint32_t a_smem = smem_u32(As);

    #define OG_AISSUE(K0, BUF) { \
        _Pragma("unroll") \
        for (int i = 0; i < 2; i++) { \
            int e = tid + i*256; \
            int kk = e >> 5, m4 = e & 31; \
            int k = (K0) + kk; \
            int sp = MODEW ? fix*HW + k : k*HW + fix; \
            const float* src = &g_v[((size_t)b*SSP + sp)*256 + c0 + m4*4]; \
            int nb = (k < HW) ? 16 : 0; \
            if (nb == 0) src = g_v; \
            uint32_t dst = a_smem + ((BUF)*16*ASP + kk*ASP + m4*4)*4; \
            CP_ASYNC16(dst, src, nb); \
        } }
    #define OG_BLOAD(K0) { \
        _Pragma("unroll") \
        for (int i = 0; i < 8; i++) { \
            int e = tid + i*256; int nn = e>>4, kk = e&15; \
            size_t srow = MODEW ? ((size_t)(b*HW+fix)*HW + nn) : ((size_t)(b*HW+nn)*HW + fix); \
            br[i] = (nn < HW) ? g_S[srow*256 + noff + (K0) + kk] : 0.f; \
        } }
    #define OG_BSTORE(BUF) { \
        _Pragma("unroll") \
        for (int i = 0; i < 8; i++) { \
            int e = tid + i*256; int nn = e>>4, kk = e&15; \
            Bs[(BUF)*16*NP2 + kk*NP2 + nn] = make_float2(br[i], br[i]); \
        } }

    OG_AISSUE(0, 0); CP_COMMIT;
    OG_BLOAD(0); OG_BSTORE(0);
    CP_WAIT0; __syncthreads();
    for (int kt = 0; kt < 8; kt++) {
        if (kt < 7) { OG_AISSUE((kt+1)*16, (kt+1)&1); CP_COMMIT; OG_BLOAD((kt+1)*16); }
        stepK16<8>(As + (kt&1)*16*ASP, Bs + (kt&1)*16*NP2, acc, tx, ty);
        if (kt < 7) { OG_BSTORE((kt+1)&1); CP_WAIT0; }
        __syncthreads();
    }
    #undef OG_AISSUE
    #undef OG_BLOAD
    #undef OG_BSTORE

    __half* O = MODEW ? g_oW : g_oH;
    #pragma unroll
    for (int mi = 0; mi < 8; mi++) {
        int p = mi>>1, h = mi&1;
        int c = c0 + ((mi<4) ? tx*4+mi : 64+tx*4+mi-4);
        float v[8];
        #pragma unroll
        for (int n = 0; n < 8; n++) {
            float2 t2 = unpack2(acc[p][n]);
            v[n] = h ? t2.y : t2.x;
        }
        __half2 q0 = __floats2half2_rn(v[0], v[1]);
        __half2 q1 = __floats2half2_rn(v[2], v[3]);
        __half2 q2 = __floats2half2_rn(v[4], v[5]);
        __half2 q3 = __floats2half2_rn(v[6], v[7]);
        uint4 u = make_uint4(*(uint32_t*)&q0, *(uint32_t*)&q1, *(uint32_t*)&q2, *(uint32_t*)&q3);
        *(uint4*)&O[((size_t)(b*256 + c)*HW + fix)*128 + ty*8] = u;
    }
}

// ---------------- 8) bilinear upsample 127->256, residual ----------------
__global__ __launch_bounds__(256) void final_kernel(const float* __restrict__ x,
                                                    const float* __restrict__ gamma,
                                                    float* __restrict__ out) {
    int bc = blockIdx.z;
    int xx = blockIdx.x * 32 + (threadIdx.x & 31);
    int yy = blockIdx.y * 8  + (threadIdx.x >> 5);
    const float sc = 126.f / 255.f;
    float yf = yy * sc; int y0 = (int)yf; float wy = yf - y0; int y1 = min(y0+1, HW-1);
    float xf = xx * sc; int x0 = (int)xf; float wx = xf - x0; int x1 = min(x0+1, HW-1);
    const __half* Ht = g_oH + (size_t)bc * HW * 128;   // [j][i]
    const __half* Wt = g_oW + (size_t)bc * HW * 128;   // [i][j]
    float h00 = __half2float(Ht[x0*128 + y0]), h01 = __half2float(Ht[x0*128 + y1]);
    float h10 = __half2float(Ht[x1*128 + y0]), h11 = __half2float(Ht[x1*128 + y1]);
    float hv = (h00*(1.f-wy) + h01*wy)*(1.f-wx) + (h10*(1.f-wy) + h11*wy)*wx;
    float w00 = __half2float(Wt[y0*128 + x0]), w01 = __half2float(Wt[y0*128 + x1]);
    float w10 = __half2float(Wt[y1*128 + x0]), w11 = __half2float(Wt[y1*128 + x1]);
    float wv = (w00*(1.f-wx) + w01*wx)*(1.f-wy) + (w10*(1.f-wx) + w11*wx)*wy;
    size_t idx = (size_t)bc * IMGSZ + yy*IMG + xx;
    out[idx] = gamma[0] * (hv + wv) + x[idx];
}

// ---------------- launch ----------------
extern "C" void kernel_launch(void* const* d_in, const int* in_sizes, int n_in,
                              void* d_out, int out_size) {
    (void)in_sizes; (void)n_in; (void)out_size;
    const float* x  = (const float*)d_in[0];
    const float* am = (const float*)d_in[1];
    const float* wd = (const float*)d_in[2];
    const float* wq = (const float*)d_in[3];
    const float* bq = (const float*)d_in[4];
    const float* wk = (const float*)d_in[5];
    const float* bk = (const float*)d_in[6];
    const float* wv = (const float*)d_in[7];
    const float* bv = (const float*)d_in[8];
    const float* gm = (const float*)d_in[9];
    float* out = (float*)d_out;

    const int SM_PIPE = 2*16*ASP*4 + 2*16*NP2*8;   // 50176 bytes

    cudaFuncSetAttribute(proj_v_kernel, cudaFuncAttributeMaxDynamicSharedMemorySize, SM_PIPE);
    cudaFuncSetAttribute(outgemm_kernel<false>, cudaFuncAttributeMaxDynamicSharedMemorySize, SM_PIPE);
    cudaFuncSetAttribute(outgemm_kernel<true>,  cudaFuncAttributeMaxDynamicSharedMemorySize, SM_PIPE);

    conv_down_kernel<<<(BB*CC*SSP + 255)/256, 256>>>(x, wd);
    resize_a_kernel<<<dim3(4, HW, BB), 256>>>(am);

    proj_qk_kernel<<<dim3(127, BB), 256>>>(wq, bq, wk, bk);
    proj_v_kernel<<<dim3(127, 2, BB), 256, SM_PIPE>>>(wv, bv);

    energy_kernel<32, false, true ><<<dim3(HW, BB), 256>>>();  // eH (masked)
    energy_kernel<32, true,  false><<<dim3(HW, BB), 256>>>();  // eW
    energy_kernel<64, false, true ><<<dim3(HW, BB), 256>>>();  // aH (masked)
    energy_kernel<64, true,  false><<<dim3(HW, BB), 256>>>();  // aW

    softmax3_kernel<<<(BB*SSP + 7)/8, 256>>>();

    outgemm_kernel<false><<<dim3(HW, 2, BB), 256, SM_PIPE>>>();
    outgemm_kernel<true ><<<dim3(HW, 2, BB), 256, SM_PIPE>>>();

    final_kernel<<<dim3(8, 32, BB*CC), 256>>>(x, gm, out);
}